// round 3
// baseline (speedup 1.0000x reference)
#include <cuda_runtime.h>
#include <cuda_bf16.h>

// LocalCrossLinearTrf: B=2, D=H=W=64, F_IN=F_OUT=8
//
// Strategy (R2): the gather stream was L1-wavefront bound (92% L1) because x
// is [v][8ch] (32B voxel stride). Pre-transpose x into channel-major planes
// with the two batches interleaved as float2 -> gather addresses are dense
// (w-stride = 1 elem) and each 8B load serves BOTH batches.

#define NVOX   262144        // 64^3
#define XB     2097152       // per-batch x/out stride in floats (64^3 * 8)

constexpr int VPB = 32;      // voxels per block
constexpr int THREADS = 256; // 8 threads (one per output j) per voxel

// scratch: xt[ch][v] = float2(x[b=0][v][ch], x[b=1][v][ch])  -- 16 MB
__device__ float2 g_xt[8 * NVOX];

// ---------------------------------------------------------------------------
// transpose: [2][v][8] f32  ->  [8][v] float2(b0,b1)
// reads coalesced (float4), writes coalesced (float2, v-contiguous per plane)
// ---------------------------------------------------------------------------
__global__ __launch_bounds__(256)
void transpose_kernel(const float* __restrict__ x)
{
    const int v = blockIdx.x * blockDim.x + threadIdx.x;   // 0..NVOX-1
    const float4* x4 = reinterpret_cast<const float4*>(x);
    const float4 a0 = x4[(size_t)v * 2];                   // b0 ch0-3
    const float4 a1 = x4[(size_t)v * 2 + 1];               // b0 ch4-7
    const float4 b0 = x4[(size_t)(XB / 4) + v * 2];        // b1 ch0-3
    const float4 b1 = x4[(size_t)(XB / 4) + v * 2 + 1];    // b1 ch4-7
    g_xt[0 * NVOX + v] = make_float2(a0.x, b0.x);
    g_xt[1 * NVOX + v] = make_float2(a0.y, b0.y);
    g_xt[2 * NVOX + v] = make_float2(a0.z, b0.z);
    g_xt[3 * NVOX + v] = make_float2(a0.w, b0.w);
    g_xt[4 * NVOX + v] = make_float2(a1.x, b1.x);
    g_xt[5 * NVOX + v] = make_float2(a1.y, b1.y);
    g_xt[6 * NVOX + v] = make_float2(a1.z, b1.z);
    g_xt[7 * NVOX + v] = make_float2(a1.w, b1.w);
}

// ---------------------------------------------------------------------------
// main kernel
// ---------------------------------------------------------------------------
__global__ __launch_bounds__(THREADS)
void lclt_kernel(const float* __restrict__ mult,
                 const float* __restrict__ trf,
                 const float* __restrict__ bias,
                 float* __restrict__ out)
{
    __shared__ float s_trf [VPB * 192];  // [vl][i*24 + j*3 + a]
    __shared__ float s_mult[VPB * 64];   // [vl][i*8 + j]
    __shared__ float s_bias[VPB * 8];    // [vl][j]

    const int vbase = blockIdx.x * VPB;

    // ---- coalesced staging (float4) ----
    {
        const float4* gt = reinterpret_cast<const float4*>(trf + (size_t)vbase * 192);
        float4* st = reinterpret_cast<float4*>(s_trf);
        #pragma unroll
        for (int k = threadIdx.x; k < VPB * 192 / 4; k += THREADS) st[k] = gt[k];

        const float4* gm = reinterpret_cast<const float4*>(mult + (size_t)vbase * 64);
        float4* sm = reinterpret_cast<float4*>(s_mult);
        #pragma unroll
        for (int k = threadIdx.x; k < VPB * 64 / 4; k += THREADS) sm[k] = gm[k];

        s_bias[threadIdx.x] = bias[(size_t)vbase * 8 + threadIdx.x];
    }
    __syncthreads();

    const int vl = threadIdx.x >> 3;   // local voxel 0..31
    const int j  = threadIdx.x & 7;    // output feature
    const int v  = vbase + vl;
    const int wc =  v        & 63;
    const int hc = (v >> 6)  & 63;
    const int dc =  v >> 12;
    const float fd = (float)dc, fh = (float)hc, fw = (float)wc;

    const float* tb = s_trf  + vl * 192 + j * 3;
    const float* mb = s_mult + vl * 64  + j;

    float acc0 = 0.f, acc1 = 0.f;

    #pragma unroll
    for (int i = 0; i < 8; ++i) {
        const float t0 = tb[i * 24 + 0];
        const float t1 = tb[i * 24 + 1];
        const float t2 = tb[i * 24 + 2];
        const float m  = mb[i * 8];

        // --- per-axis corner indices + weights (neurite convention) ---
        // axis D  (stride 4096 in the channel plane)
        float loc = fd + t0;
        float cl  = fminf(fmaxf(loc, 0.f), 63.f);
        int   l0  = (int)fminf(fmaxf(floorf(loc), 0.f), 63.f);
        int   l1  = min(l0 + 1, 63);
        float d1d = (float)l1 - cl;
        float d0d = 1.f - d1d;
        int   oD0 = l0 << 12, oD1 = l1 << 12;
        // axis H  (stride 64)
        loc = fh + t1;
        cl  = fminf(fmaxf(loc, 0.f), 63.f);
        l0  = (int)fminf(fmaxf(floorf(loc), 0.f), 63.f);
        l1  = min(l0 + 1, 63);
        float d1h = (float)l1 - cl;
        float d0h = 1.f - d1h;
        int   oH0 = l0 << 6, oH1 = l1 << 6;
        // axis W  (stride 1)
        loc = fw + t2;
        cl  = fminf(fmaxf(loc, 0.f), 63.f);
        l0  = (int)fminf(fmaxf(floorf(loc), 0.f), 63.f);
        l1  = min(l0 + 1, 63);
        float d1w = (float)l1 - cl;
        float d0w = 1.f - d1w;
        const int oW0 = l0, oW1 = l1;

        // combined DH weights / offsets (c=0 -> l0 w/ weight d1; c=1 -> l1 w/ d0)
        const float w00 = d1d * d1h, w01 = d1d * d0h, w10 = d0d * d1h, w11 = d0d * d0h;
        const int   o00 = oD0 + oH0, o01 = oD0 + oH1, o10 = oD1 + oH0, o11 = oD1 + oH1;

        const float2* cb = g_xt + i * NVOX;   // channel plane, both batches

        float s0 = 0.f, s1 = 0.f;
        {
            float wl, wr; float2 p;
            wl = w00 * d1w; wr = w00 * d0w;
            p = __ldg(cb + o00 + oW0); s0 = fmaf(wl, p.x, s0); s1 = fmaf(wl, p.y, s1);
            p = __ldg(cb + o00 + oW1); s0 = fmaf(wr, p.x, s0); s1 = fmaf(wr, p.y, s1);
            wl = w01 * d1w; wr = w01 * d0w;
            p = __ldg(cb + o01 + oW0); s0 = fmaf(wl, p.x, s0); s1 = fmaf(wl, p.y, s1);
            p = __ldg(cb + o01 + oW1); s0 = fmaf(wr, p.x, s0); s1 = fmaf(wr, p.y, s1);
            wl = w10 * d1w; wr = w10 * d0w;
            p = __ldg(cb + o10 + oW0); s0 = fmaf(wl, p.x, s0); s1 = fmaf(wl, p.y, s1);
            p = __ldg(cb + o10 + oW1); s0 = fmaf(wr, p.x, s0); s1 = fmaf(wr, p.y, s1);
            wl = w11 * d1w; wr = w11 * d0w;
            p = __ldg(cb + o11 + oW0); s0 = fmaf(wl, p.x, s0); s1 = fmaf(wl, p.y, s1);
            p = __ldg(cb + o11 + oW1); s0 = fmaf(wr, p.x, s0); s1 = fmaf(wr, p.y, s1);
        }

        acc0 = fmaf(m, s0, acc0);
        acc1 = fmaf(m, s1, acc1);
    }

    const float bterm = 8.f * s_bias[vl * 8 + j];
    const int oidx = v * 8 + j;
    out[oidx]      = acc0 + bterm;
    out[oidx + XB] = acc1 + bterm;
}

extern "C" void kernel_launch(void* const* d_in, const int* in_sizes, int n_in,
                              void* d_out, int out_size)
{
    const float* x    = (const float*)d_in[0];
    const float* mult = (const float*)d_in[1];
    const float* trf  = (const float*)d_in[2];
    const float* bias = (const float*)d_in[3];
    float* out = (float*)d_out;

    transpose_kernel<<<NVOX / 256, 256>>>(x);
    lclt_kernel<<<NVOX / VPB, THREADS>>>(mult, trf, bias, out);
}

// round 5
// speedup vs baseline: 1.6433x; 1.6433x over previous
#include <cuda_runtime.h>
#include <cuda_bf16.h>

// LocalCrossLinearTrf: B=2, D=H=W=64, F_IN=F_OUT=8
//
// R3: (a) kill 4-way smem bank conflicts on the trf/mult reads via modular
// row padding (stride 216 == 24 mod 32 -> bank bijection over the warp's
// (vl,j) pairs; stride 72 == 8 mod 32 for mult); (b) gather x via 32-bit
// loads from two batch-separated channel-major planes (duplicate/dense
// addresses -> ~1 sector per LDG.32, avoiding the >=2-wavefront cost of
// 64-bit loads).

#define NVOX   262144        // 64^3
#define XB     2097152       // per-batch x/out stride in floats (64^3 * 8)

constexpr int VPB = 32;      // voxels per block
constexpr int THREADS = 256; // 8 threads (one per output j) per voxel

constexpr int TRF_STRIDE  = 216; // floats/row; 216 mod 32 = 24 -> bijective banks
constexpr int MULT_STRIDE = 72;  // floats/row; 72 mod 32 = 8  -> bijective banks

// scratch: per-batch channel-major planes x[b][ch][v]  (8 MB each)
__device__ float g_x0[8 * NVOX];
__device__ float g_x1[8 * NVOX];

// ---------------------------------------------------------------------------
// transpose: [2][v][8] f32  ->  two [8][v] planes
// ---------------------------------------------------------------------------
__global__ __launch_bounds__(256)
void transpose_kernel(const float* __restrict__ x)
{
    const int v = blockIdx.x * blockDim.x + threadIdx.x;   // 0..NVOX-1
    const float4* x4 = reinterpret_cast<const float4*>(x);
    const float4 a0 = x4[(size_t)v * 2];                   // b0 ch0-3
    const float4 a1 = x4[(size_t)v * 2 + 1];               // b0 ch4-7
    const float4 b0 = x4[(size_t)(XB / 4) + v * 2];        // b1 ch0-3
    const float4 b1 = x4[(size_t)(XB / 4) + v * 2 + 1];    // b1 ch4-7
    g_x0[0 * NVOX + v] = a0.x;  g_x1[0 * NVOX + v] = b0.x;
    g_x0[1 * NVOX + v] = a0.y;  g_x1[1 * NVOX + v] = b0.y;
    g_x0[2 * NVOX + v] = a0.z;  g_x1[2 * NVOX + v] = b0.z;
    g_x0[3 * NVOX + v] = a0.w;  g_x1[3 * NVOX + v] = b0.w;
    g_x0[4 * NVOX + v] = a1.x;  g_x1[4 * NVOX + v] = b1.x;
    g_x0[5 * NVOX + v] = a1.y;  g_x1[5 * NVOX + v] = b1.y;
    g_x0[6 * NVOX + v] = a1.z;  g_x1[6 * NVOX + v] = b1.z;
    g_x0[7 * NVOX + v] = a1.w;  g_x1[7 * NVOX + v] = b1.w;
}

// ---------------------------------------------------------------------------
// main kernel
// ---------------------------------------------------------------------------
__global__ __launch_bounds__(THREADS)
void lclt_kernel(const float* __restrict__ mult,
                 const float* __restrict__ trf,
                 const float* __restrict__ bias,
                 float* __restrict__ out)
{
    __shared__ float s_trf [VPB * TRF_STRIDE];   // [vl](pad216)  i*24 + j*3 + a
    __shared__ float s_mult[VPB * MULT_STRIDE];  // [vl](pad72)   i*8 + j
    __shared__ float s_bias[VPB * 8];            // [vl][j]

    const int vbase = blockIdx.x * VPB;

    // ---- coalesced staging (float4), conflict-free padded rows ----
    {
        const float4* gt = reinterpret_cast<const float4*>(trf + (size_t)vbase * 192);
        float4* st = reinterpret_cast<float4*>(s_trf);
        #pragma unroll
        for (int k = threadIdx.x; k < VPB * 48; k += THREADS) {  // 1536 float4
            const int vl = k / 48, c = k % 48;
            st[vl * (TRF_STRIDE / 4) + c] = gt[k];
        }
        const float4* gm = reinterpret_cast<const float4*>(mult + (size_t)vbase * 64);
        float4* sm = reinterpret_cast<float4*>(s_mult);
        #pragma unroll
        for (int k = threadIdx.x; k < VPB * 16; k += THREADS) {  // 512 float4
            const int vl = k / 16, c = k % 16;
            sm[vl * (MULT_STRIDE / 4) + c] = gm[k];
        }
        s_bias[threadIdx.x] = bias[(size_t)vbase * 8 + threadIdx.x];
    }
    __syncthreads();

    const int vl = threadIdx.x >> 3;   // local voxel 0..31
    const int j  = threadIdx.x & 7;    // output feature
    const int v  = vbase + vl;
    const int wc =  v        & 63;
    const int hc = (v >> 6)  & 63;
    const int dc =  v >> 12;
    const float fd = (float)dc, fh = (float)hc, fw = (float)wc;

    const float* tb = s_trf  + vl * TRF_STRIDE  + j * 3;
    const float* mb = s_mult + vl * MULT_STRIDE + j;

    float acc0 = 0.f, acc1 = 0.f;

    #pragma unroll
    for (int i = 0; i < 8; ++i) {
        const float t0 = tb[i * 24 + 0];
        const float t1 = tb[i * 24 + 1];
        const float t2 = tb[i * 24 + 2];
        const float m  = mb[i * 8];

        // --- per-axis corner indices + weights (neurite convention) ---
        // floor(clamp(loc)) == clamp(floor(loc)) for loc in (-1, 64)
        // axis D (stride 4096 in plane)
        float cl  = fminf(fmaxf(fd + t0, 0.f), 63.f);
        int   l0  = __float2int_rd(cl);
        int   l1  = min(l0 + 1, 63);
        float d1d = (float)l1 - cl;
        float d0d = 1.f - d1d;
        int   oD0 = l0 << 12, oD1 = l1 << 12;
        // axis H (stride 64)
        cl  = fminf(fmaxf(fh + t1, 0.f), 63.f);
        l0  = __float2int_rd(cl);
        l1  = min(l0 + 1, 63);
        float d1h = (float)l1 - cl;
        float d0h = 1.f - d1h;
        int   oH0 = l0 << 6, oH1 = l1 << 6;
        // axis W (stride 1)
        cl  = fminf(fmaxf(fw + t2, 0.f), 63.f);
        l0  = __float2int_rd(cl);
        l1  = min(l0 + 1, 63);
        float d1w = (float)l1 - cl;
        float d0w = 1.f - d1w;
        const int oW0 = l0, oW1 = l1;

        // combined DH weights / offsets (c=0 -> l0 w/ weight d1; c=1 -> l1 w/ d0)
        const float w00 = d1d * d1h, w01 = d1d * d0h, w10 = d0d * d1h, w11 = d0d * d0h;
        const int   o00 = oD0 + oH0, o01 = oD0 + oH1, o10 = oD1 + oH0, o11 = oD1 + oH1;

        const float* p0 = g_x0 + i * NVOX;   // batch 0 channel plane
        const float* p1 = g_x1 + i * NVOX;   // batch 1 channel plane

        float s0 = 0.f, s1 = 0.f;
        {
            float wl, wr; int il, ir;
            wl = w00 * d1w; wr = w00 * d0w; il = o00 + oW0; ir = o00 + oW1;
            s0 = fmaf(wl, __ldg(p0 + il), s0); s0 = fmaf(wr, __ldg(p0 + ir), s0);
            s1 = fmaf(wl, __ldg(p1 + il), s1); s1 = fmaf(wr, __ldg(p1 + ir), s1);
            wl = w01 * d1w; wr = w01 * d0w; il = o01 + oW0; ir = o01 + oW1;
            s0 = fmaf(wl, __ldg(p0 + il), s0); s0 = fmaf(wr, __ldg(p0 + ir), s0);
            s1 = fmaf(wl, __ldg(p1 + il), s1); s1 = fmaf(wr, __ldg(p1 + ir), s1);
            wl = w10 * d1w; wr = w10 * d0w; il = o10 + oW0; ir = o10 + oW1;
            s0 = fmaf(wl, __ldg(p0 + il), s0); s0 = fmaf(wr, __ldg(p0 + ir), s0);
            s1 = fmaf(wl, __ldg(p1 + il), s1); s1 = fmaf(wr, __ldg(p1 + ir), s1);
            wl = w11 * d1w; wr = w11 * d0w; il = o11 + oW0; ir = o11 + oW1;
            s0 = fmaf(wl, __ldg(p0 + il), s0); s0 = fmaf(wr, __ldg(p0 + ir), s0);
            s1 = fmaf(wl, __ldg(p1 + il), s1); s1 = fmaf(wr, __ldg(p1 + ir), s1);
        }

        acc0 = fmaf(m, s0, acc0);
        acc1 = fmaf(m, s1, acc1);
    }

    const float bterm = 8.f * s_bias[vl * 8 + j];
    const int oidx = v * 8 + j;
    out[oidx]      = acc0 + bterm;
    out[oidx + XB] = acc1 + bterm;
}

extern "C" void kernel_launch(void* const* d_in, const int* in_sizes, int n_in,
                              void* d_out, int out_size)
{
    const float* x    = (const float*)d_in[0];
    const float* mult = (const float*)d_in[1];
    const float* trf  = (const float*)d_in[2];
    const float* bias = (const float*)d_in[3];
    float* out = (float*)d_out;

    transpose_kernel<<<NVOX / 256, 256>>>(x);
    lclt_kernel<<<NVOX / VPB, THREADS>>>(mult, trf, bias, out);
}